// round 15
// baseline (speedup 1.0000x reference)
#include <cuda_runtime.h>
#include <cuda_bf16.h>

#define NN 50000
#define NE 800000
#define NET (NE + NN)
#define HEADS 4
#define HID 64
#define D1 256            // HEADS*HID
#define IND 128
#define EMB 128
#define NG 64

typedef unsigned long long ull;

// ---------------- scratch ----------------
__device__ __align__(16) __nv_bfloat16 g_h1[(size_t)NN * D1];   // bf16 messages L1
__device__ __align__(16) float         g_act1[(size_t)NN * D1]; // fp32 (gemm2 input)
__device__ __align__(16) __nv_bfloat16 g_h2[(size_t)NN * EMB];  // bf16 messages L2
__device__ __align__(16) float g_as1[NN * HEADS];
__device__ __align__(16) float g_ad1[NN * HEADS];
__device__ __align__(16) float g_as2[NN];
__device__ __align__(16) float g_ad2[NN];
__device__ __align__(16) float g_pool[NG * EMB];
__device__ __align__(16) float g_cnt[NG];
__device__ __align__(16) int   g_src[NET];
__device__ __align__(16) int   g_dst[NET];
__device__ __align__(16) int   g_batch[NN];
__device__ __align__(16) int   g_rowptr[NN + 1];
__device__ __align__(16) int   g_wp[NN];     // zeroed by tail kernel each run
__device__ __align__(16) int   g_csrc[NET];

// ---------------- helpers ----------------
__device__ __forceinline__ float elu1(float x)  { return x > 0.f ? x : expm1f(x); }
__device__ __forceinline__ float lrelu(float x) { return x > 0.f ? x : 0.2f * x; }

__device__ __forceinline__ void red4(float* p, float a, float b, float c, float d) {
    asm volatile("red.global.add.v4.f32 [%0], {%1, %2, %3, %4};"
                 :: "l"(p), "f"(a), "f"(b), "f"(c), "f"(d) : "memory");
}
__device__ __forceinline__ void ffma2(ull& d, ull a, ull b) {
    asm("fma.rn.f32x2 %0, %1, %2, %0;" : "+l"(d) : "l"(a), "l"(b));
}
__device__ __forceinline__ ull pack2(float lo, float hi) {
    ull r; asm("mov.b64 %0, {%1, %2};" : "=l"(r) : "f"(lo), "f"(hi)); return r;
}
__device__ __forceinline__ void unpack2(float& lo, float& hi, ull v) {
    asm("mov.b64 {%0, %1}, %2;" : "=f"(lo), "=f"(hi) : "l"(v));
}
__device__ __forceinline__ unsigned bfpack(float lo, float hi) {
    unsigned r;
    asm("cvt.rn.bf16x2.f32 %0, %1, %2;" : "=r"(r) : "f"(hi), "f"(lo));
    return r;
}
__device__ __forceinline__ float bflo(unsigned u) { return __uint_as_float(u << 16); }
__device__ __forceinline__ float bfhi(unsigned u) { return __uint_as_float(u & 0xffff0000u); }

// ---------------- prep (indices + batch + degree count) ----------------
__global__ __launch_bounds__(256) void prep_kernel(const void* ei_raw, const void* b_raw) {
    const int*       e32 = (const int*)ei_raw;
    const long long* e64 = (const long long*)ei_raw;
    bool is64 = true;
#pragma unroll
    for (int i = 0; i < 16; i++) is64 &= (e32[2 * i + 1] == 0);

    int idx = blockIdx.x * blockDim.x + threadIdx.x;
    if (idx < NET) {
        int s, d;
        if (idx < NE) {
            if (is64) { s = (int)e64[idx]; d = (int)e64[NE + idx]; }
            else      { s = e32[idx];      d = e32[NE + idx]; }
        } else { s = d = idx - NE; }
        g_src[idx] = s;
        g_dst[idx] = d;
        atomicAdd(&g_wp[d], 1);
    }
    if (idx < NN) {
        int b = is64 ? (int)((const long long*)b_raw)[idx] : ((const int*)b_raw)[idx];
        g_batch[idx] = b;
        atomicAdd(&g_cnt[b], 1.f);
    }
}

__global__ __launch_bounds__(1024) void scan_kernel() {
    __shared__ int part[1024];
    int t = threadIdx.x;
    const int CH = (NN + 1023) / 1024;
    int beg = t * CH, end = min(beg + CH, NN);
    int sum = 0;
    for (int i = beg; i < end; i++) sum += g_wp[i];
    part[t] = sum;
    __syncthreads();
    for (int off = 1; off < 1024; off <<= 1) {
        int v = (t >= off) ? part[t - off] : 0;
        __syncthreads();
        part[t] += v;
        __syncthreads();
    }
    int run = (t == 0) ? 0 : part[t - 1];
    for (int i = beg; i < end; i++) {
        int c = g_wp[i];
        g_rowptr[i] = run;
        g_wp[i] = run;
        run += c;
    }
    if (t == 1023) g_rowptr[NN] = run;
}

__global__ __launch_bounds__(256) void fill_kernel() {
    int e = blockIdx.x * blockDim.x + threadIdx.x;
    if (e >= NET) return;
    int pos = atomicAdd(&g_wp[g_dst[e]], 1);
    g_csrc[pos] = g_src[e];
}

// ---------------- f32x2 GEMM + fused attention-dot epilogue (R14 proven) ----------------
__global__ __launch_bounds__(128, 4) void gemm_kernel(
    const float* __restrict__ A, const float* __restrict__ B, __nv_bfloat16* __restrict__ C,
    int M, int N, int K,
    const float* __restrict__ avec, const float* __restrict__ dvec,
    float* __restrict__ as_out, float* __restrict__ ad_out, int multihead)
{
    __shared__ float As[16][68];
    __shared__ float Bs[16][132];

    int tid = threadIdx.x;
    int lane = tid & 31;
    int rowBase = blockIdx.x * 64;
    int colBase = blockIdx.y * 128;
    int tx = tid & 15;
    int ty = tid >> 4;

    ull acc[4][8];
#pragma unroll
    for (int p = 0; p < 4; p++)
#pragma unroll
        for (int j = 0; j < 8; j++) acc[p][j] = 0ull;

    for (int k0 = 0; k0 < K; k0 += 16) {
#pragma unroll
        for (int i = 0; i < 2; i++) {
            int fid = tid + 128 * i;
            int r = fid >> 2, kq = (fid & 3) * 4;
            int row = rowBase + r;
            float4 v = make_float4(0.f, 0.f, 0.f, 0.f);
            if (row < M) v = *(const float4*)(A + (long long)row * K + k0 + kq);
            As[kq + 0][r] = v.x; As[kq + 1][r] = v.y;
            As[kq + 2][r] = v.z; As[kq + 3][r] = v.w;
        }
#pragma unroll
        for (int i = 0; i < 4; i++) {
            int fid = tid + 128 * i;
            int rw = fid >> 5, cq = fid & 31;
            *(float4*)&Bs[rw][cq * 4] =
                *(const float4*)(B + (long long)(k0 + rw) * N + colBase + cq * 4);
        }
        __syncthreads();
#pragma unroll
        for (int kk = 0; kk < 16; kk++) {
            ulonglong2 a01 = *(const ulonglong2*)&As[kk][ty * 8];
            ulonglong2 a23 = *(const ulonglong2*)&As[kk][ty * 8 + 4];
            float4 b0 = *(const float4*)&Bs[kk][tx * 4];
            float4 b1 = *(const float4*)&Bs[kk][64 + tx * 4];
            ull rb[8];
            rb[0] = pack2(b0.x, b0.x); rb[1] = pack2(b0.y, b0.y);
            rb[2] = pack2(b0.z, b0.z); rb[3] = pack2(b0.w, b0.w);
            rb[4] = pack2(b1.x, b1.x); rb[5] = pack2(b1.y, b1.y);
            rb[6] = pack2(b1.z, b1.z); rb[7] = pack2(b1.w, b1.w);
            ull ra[4] = {a01.x, a01.y, a23.x, a23.y};
#pragma unroll
            for (int p = 0; p < 4; p++)
#pragma unroll
                for (int j = 0; j < 8; j++) ffma2(acc[p][j], ra[p], rb[j]);
        }
        __syncthreads();
    }

    float4 av0 = *(const float4*)(avec + colBase + tx * 4);
    float4 av1 = *(const float4*)(avec + colBase + 64 + tx * 4);
    float4 dv0 = *(const float4*)(dvec + colBase + tx * 4);
    float4 dv1 = *(const float4*)(dvec + colBase + 64 + tx * 4);
    float ds0[8], ds1[8], dd0[8], dd1[8];

#pragma unroll
    for (int p = 0; p < 4; p++) {
        float lo[8], hi[8];
#pragma unroll
        for (int j = 0; j < 8; j++) unpack2(lo[j], hi[j], acc[p][j]);
        int m0 = rowBase + ty * 8 + 2 * p;
        long long cb = (long long)m0 * N + colBase + tx * 4;
        if (m0 < M) {
            uint2 u0 = make_uint2(bfpack(lo[0], lo[1]), bfpack(lo[2], lo[3]));
            uint2 u1 = make_uint2(bfpack(lo[4], lo[5]), bfpack(lo[6], lo[7]));
            *(uint2*)(C + cb)      = u0;
            *(uint2*)(C + cb + 64) = u1;
        }
        if (m0 + 1 < M) {
            uint2 u0 = make_uint2(bfpack(hi[0], hi[1]), bfpack(hi[2], hi[3]));
            uint2 u1 = make_uint2(bfpack(hi[4], hi[5]), bfpack(hi[6], hi[7]));
            *(uint2*)(C + cb + N)      = u0;
            *(uint2*)(C + cb + N + 64) = u1;
        }
        ds0[2*p]   = lo[0]*av0.x + lo[1]*av0.y + lo[2]*av0.z + lo[3]*av0.w;
        ds1[2*p]   = lo[4]*av1.x + lo[5]*av1.y + lo[6]*av1.z + lo[7]*av1.w;
        dd0[2*p]   = lo[0]*dv0.x + lo[1]*dv0.y + lo[2]*dv0.z + lo[3]*dv0.w;
        dd1[2*p]   = lo[4]*dv1.x + lo[5]*dv1.y + lo[6]*dv1.z + lo[7]*dv1.w;
        ds0[2*p+1] = hi[0]*av0.x + hi[1]*av0.y + hi[2]*av0.z + hi[3]*av0.w;
        ds1[2*p+1] = hi[4]*av1.x + hi[5]*av1.y + hi[6]*av1.z + hi[7]*av1.w;
        dd0[2*p+1] = hi[0]*dv0.x + hi[1]*dv0.y + hi[2]*dv0.z + hi[3]*dv0.w;
        dd1[2*p+1] = hi[4]*dv1.x + hi[5]*dv1.y + hi[6]*dv1.z + hi[7]*dv1.w;
    }
    if (!multihead) {
#pragma unroll
        for (int rr = 0; rr < 8; rr++) { ds0[rr] += ds1[rr]; dd0[rr] += dd1[rr]; }
    }
#pragma unroll
    for (int rr = 0; rr < 8; rr++) {
#pragma unroll
        for (int off = 1; off <= 8; off <<= 1) {
            ds0[rr] += __shfl_xor_sync(0xffffffffu, ds0[rr], off);
            dd0[rr] += __shfl_xor_sync(0xffffffffu, dd0[rr], off);
        }
        if (multihead) {
#pragma unroll
            for (int off = 1; off <= 8; off <<= 1) {
                ds1[rr] += __shfl_xor_sync(0xffffffffu, ds1[rr], off);
                dd1[rr] += __shfl_xor_sync(0xffffffffu, dd1[rr], off);
            }
        }
    }
    int rowb = rowBase + ty * 8;
    if ((lane & 15) == 0) {
        if (multihead) {
            int h0 = colBase >> 6;
#pragma unroll
            for (int rr = 0; rr < 8; rr++) {
                int row = rowb + rr;
                if (row < M) {
                    as_out[row * 4 + h0]     = ds0[rr];
                    as_out[row * 4 + h0 + 1] = ds1[rr];
                    ad_out[row * 4 + h0]     = dd0[rr];
                    ad_out[row * 4 + h0 + 1] = dd1[rr];
                }
            }
        } else {
#pragma unroll
            for (int rr = 0; rr < 8; rr++) {
                int row = rowb + rr;
                if (row < M) {
                    as_out[row] = ds0[rr];
                    ad_out[row] = dd0[rr];
                }
            }
        }
    }
}

// ---------------- CSR aggregation, layer 1: TWO warps per dst node ----------------
// warp half h covers cols h*128..h*128+127 (heads 2h, 2h+1); per-edge gather
// is uint2 (8B/lane, 256B/warp). Doubles node-level parallelism vs R14.
__global__ __launch_bounds__(256) void agg1_kernel(const float* __restrict__ b1) {
    int gw = (blockIdx.x * blockDim.x + threadIdx.x) >> 5;
    int d = gw >> 1, half = gw & 1;
    int lane = threadIdx.x & 31;
    if (d >= NN) return;
    int head = half * 2 + (lane >> 4);
    int col = half * 128 + lane * 4;
    float ad = g_ad1[d * 4 + head];
    int beg = g_rowptr[d], end = g_rowptr[d + 1];
    float z = 0.f;
    float a0 = 0.f, a1 = 0.f, a2 = 0.f, a3 = 0.f;
    for (int i = beg; i < end; i++) {
        int s = g_csrc[i];
        float w = __expf(lrelu(g_as1[s * 4 + head] + ad));
        z += w;
        uint2 v = *(const uint2*)(g_h1 + (size_t)s * D1 + col);   // 4 bf16
        a0 += w * bflo(v.x); a1 += w * bfhi(v.x);
        a2 += w * bflo(v.y); a3 += w * bfhi(v.y);
    }
    float inv = 1.f / z;
    float4 c = *(const float4*)(b1 + col);
    float4 o;
    o.x = elu1(a0 * inv + c.x); o.y = elu1(a1 * inv + c.y);
    o.z = elu1(a2 * inv + c.z); o.w = elu1(a3 * inv + c.w);
    *(float4*)(g_act1 + (size_t)d * D1 + col) = o;
}

// layer 2 (R11/R14 proven form)
__global__ __launch_bounds__(256) void agg2_kernel(const float* __restrict__ b2) {
    int d = (blockIdx.x * blockDim.x + threadIdx.x) >> 5;
    int lane = threadIdx.x & 31;
    if (d >= NN) return;
    float ad = g_ad2[d];
    int beg = g_rowptr[d], end = g_rowptr[d + 1];
    float z = 0.f;
    float a[4] = {0.f, 0.f, 0.f, 0.f};
    for (int i = beg; i < end; i++) {
        int s = g_csrc[i];
        float w = __expf(lrelu(g_as2[s] + ad));
        z += w;
        uint2 v = *(const uint2*)(g_h2 + (size_t)s * EMB + lane * 4);
        a[0] += w * bflo(v.x); a[1] += w * bfhi(v.x);
        a[2] += w * bflo(v.y); a[3] += w * bfhi(v.y);
    }
    float inv = 1.f / z;
    float4 c = ((const float4*)b2)[lane];
    float o0 = elu1(a[0] * inv + c.x), o1 = elu1(a[1] * inv + c.y);
    float o2 = elu1(a[2] * inv + c.z), o3 = elu1(a[3] * inv + c.w);
    int b = g_batch[d];
    red4(&g_pool[b * EMB + lane * 4], o0, o1, o2, o3);
}

// final divide + re-zero accumulator state for next graph replay
__global__ __launch_bounds__(256) void tail_kernel(float* __restrict__ out) {
    int i = blockIdx.x * blockDim.x + threadIdx.x;
    if (i < NG * EMB) {
        out[i] = g_pool[i] / fmaxf(g_cnt[i >> 7], 1.f);
        g_pool[i] = 0.f;
    }
    if (i < NN)  g_wp[i]  = 0;
    if (i < NG)  g_cnt[i] = 0.f;
}

// ---------------- launcher ----------------
extern "C" void kernel_launch(void* const* d_in, const int* in_sizes, int n_in,
                              void* d_out, int out_size)
{
    const float* x      = (const float*)d_in[0];
    const void*  ei     = d_in[1];
    const void*  batch  = d_in[3];
    const float* W1     = (const float*)d_in[4];
    const float* a_src1 = (const float*)d_in[5];
    const float* a_dst1 = (const float*)d_in[6];
    const float* b1     = (const float*)d_in[7];
    const float* W2     = (const float*)d_in[8];
    const float* a_src2 = (const float*)d_in[9];
    const float* a_dst2 = (const float*)d_in[10];
    const float* b2     = (const float*)d_in[11];
    float*       out    = (float*)d_out;

    __nv_bfloat16 *p_h1, *p_h2;
    float *p_act1, *p_as1, *p_ad1, *p_as2, *p_ad2;
    cudaGetSymbolAddress((void**)&p_h1,   g_h1);
    cudaGetSymbolAddress((void**)&p_act1, g_act1);
    cudaGetSymbolAddress((void**)&p_h2,   g_h2);
    cudaGetSymbolAddress((void**)&p_as1,  g_as1);
    cudaGetSymbolAddress((void**)&p_ad1,  g_ad1);
    cudaGetSymbolAddress((void**)&p_as2,  g_as2);
    cudaGetSymbolAddress((void**)&p_ad2,  g_ad2);

    static cudaStream_t s_side = nullptr;
    static cudaEvent_t  ev_fork = nullptr, ev_join = nullptr;
    if (!s_side) {
        cudaStreamCreateWithFlags(&s_side, cudaStreamNonBlocking);
        cudaEventCreateWithFlags(&ev_fork, cudaEventDisableTiming);
        cudaEventCreateWithFlags(&ev_join, cudaEventDisableTiming);
    }

    // fork: CSR build concurrent with GEMM1; gemm1 4th-submitted (profile sentinel)
    cudaEventRecord(ev_fork, 0);
    cudaStreamWaitEvent(s_side, ev_fork, 0);
    prep_kernel<<<(NET + 255) / 256, 256, 0, s_side>>>(ei, batch);   // 1
    scan_kernel<<<1, 1024, 0, s_side>>>();                           // 2
    fill_kernel<<<(NET + 255) / 256, 256, 0, s_side>>>();            // 3
    cudaEventRecord(ev_join, s_side);

    gemm_kernel<<<dim3((NN + 63) / 64, D1 / 128), 128>>>(            // 4  <- profiled
        x, W1, p_h1, NN, D1, IND, a_src1, a_dst1, p_as1, p_ad1, 1);

    cudaStreamWaitEvent(0, ev_join, 0);
    agg1_kernel<<<(2 * NN + 7) / 8, 256>>>(b1);                      // 5

    gemm_kernel<<<dim3((NN + 63) / 64, EMB / 128), 128>>>(           // 6
        p_act1, W2, p_h2, NN, EMB, D1, a_src2, a_dst2, p_as2, p_ad2, 0);
    agg2_kernel<<<(NN + 7) / 8, 256>>>(b2);                          // 7
    tail_kernel<<<(NN + 255) / 256, 256>>>(out);                     // 8
}

// round 16
// speedup vs baseline: 1.3327x; 1.3327x over previous
#include <cuda_runtime.h>
#include <cuda_bf16.h>

#define NN 50000
#define NE 800000
#define NET (NE + NN)
#define HEADS 4
#define HID 64
#define D1 256            // HEADS*HID
#define IND 128
#define EMB 128
#define NG 64

typedef unsigned long long ull;

// ---------------- scratch ----------------
__device__ __align__(16) __nv_bfloat16 g_h1[(size_t)NN * D1];   // bf16 messages L1
__device__ __align__(16) float         g_act1[(size_t)NN * D1]; // fp32 (gemm2 input)
__device__ __align__(16) __nv_bfloat16 g_h2[(size_t)NN * EMB];  // bf16 messages L2
__device__ __align__(16) float g_as1[NN * HEADS];
__device__ __align__(16) float g_ad1[NN * HEADS];
__device__ __align__(16) float g_as2[NN];
__device__ __align__(16) float g_ad2[NN];
__device__ __align__(16) float g_pool[NG * EMB];
__device__ __align__(16) float g_cnt[NG];
__device__ __align__(16) int   g_src[NET];
__device__ __align__(16) int   g_dst[NET];
__device__ __align__(16) int   g_batch[NN];
__device__ __align__(16) int   g_rowptr[NN + 1];
__device__ __align__(16) int   g_wp[NN];     // zeroed by tail kernel each run
__device__ __align__(16) int   g_csrc[NET];
__device__ int g_blkdone;                    // prepscan arrival counter (self-resetting)

// ---------------- helpers ----------------
__device__ __forceinline__ float elu1(float x)  { return x > 0.f ? x : expm1f(x); }
__device__ __forceinline__ float lrelu(float x) { return x > 0.f ? x : 0.2f * x; }

__device__ __forceinline__ void red4(float* p, float a, float b, float c, float d) {
    asm volatile("red.global.add.v4.f32 [%0], {%1, %2, %3, %4};"
                 :: "l"(p), "f"(a), "f"(b), "f"(c), "f"(d) : "memory");
}
__device__ __forceinline__ void ffma2(ull& d, ull a, ull b) {
    asm("fma.rn.f32x2 %0, %1, %2, %0;" : "+l"(d) : "l"(a), "l"(b));
}
__device__ __forceinline__ ull pack2(float lo, float hi) {
    ull r; asm("mov.b64 %0, {%1, %2};" : "=l"(r) : "f"(lo), "f"(hi)); return r;
}
__device__ __forceinline__ void unpack2(float& lo, float& hi, ull v) {
    asm("mov.b64 {%0, %1}, %2;" : "=f"(lo), "=f"(hi) : "l"(v));
}
__device__ __forceinline__ unsigned bfpack(float lo, float hi) {
    unsigned r;
    asm("cvt.rn.bf16x2.f32 %0, %1, %2;" : "=r"(r) : "f"(hi), "f"(lo));
    return r;
}
__device__ __forceinline__ float bflo(unsigned u) { return __uint_as_float(u << 16); }
__device__ __forceinline__ float bfhi(unsigned u) { return __uint_as_float(u & 0xffff0000u); }

// ---------------- prep + scan (fused; last block scans degrees) ----------------
__global__ __launch_bounds__(256) void prepscan_kernel(const void* ei_raw, const void* b_raw) {
    const int*       e32 = (const int*)ei_raw;
    const long long* e64 = (const long long*)ei_raw;
    bool is64 = true;
#pragma unroll
    for (int i = 0; i < 16; i++) is64 &= (e32[2 * i + 1] == 0);

    int idx = blockIdx.x * blockDim.x + threadIdx.x;
    if (idx < NET) {
        int s, d;
        if (idx < NE) {
            if (is64) { s = (int)e64[idx]; d = (int)e64[NE + idx]; }
            else      { s = e32[idx];      d = e32[NE + idx]; }
        } else { s = d = idx - NE; }
        g_src[idx] = s;
        g_dst[idx] = d;
        atomicAdd(&g_wp[d], 1);
    }
    if (idx < NN) {
        int b = is64 ? (int)((const long long*)b_raw)[idx] : ((const int*)b_raw)[idx];
        g_batch[idx] = b;
        atomicAdd(&g_cnt[b], 1.f);
    }

    // last-block barrier
    __shared__ int s_last;
    __shared__ int part[256];
    __threadfence();
    __syncthreads();
    if (threadIdx.x == 0)
        s_last = (atomicAdd(&g_blkdone, 1) == (int)gridDim.x - 1);
    __syncthreads();
    if (!s_last) return;

    // exclusive scan of degrees -> rowptr; g_wp becomes write cursor
    __threadfence();
    int t = threadIdx.x;
    const int CH = (NN + 255) / 256;   // 196
    int beg = t * CH, end = min(beg + CH, NN);
    int sum = 0;
    for (int i = beg; i < end; i++) sum += g_wp[i];
    part[t] = sum;
    __syncthreads();
    for (int off = 1; off < 256; off <<= 1) {
        int v = (t >= off) ? part[t - off] : 0;
        __syncthreads();
        part[t] += v;
        __syncthreads();
    }
    int run = (t == 0) ? 0 : part[t - 1];
    for (int i = beg; i < end; i++) {
        int c = g_wp[i];
        g_rowptr[i] = run;
        g_wp[i] = run;
        run += c;
    }
    if (t == 255) g_rowptr[NN] = run;
    if (t == 0) g_blkdone = 0;   // reset for next graph replay
}

__global__ __launch_bounds__(256) void fill_kernel() {
    int e = blockIdx.x * blockDim.x + threadIdx.x;
    if (e >= NET) return;
    int pos = atomicAdd(&g_wp[g_dst[e]], 1);
    g_csrc[pos] = g_src[e];
}

// ---------------- f32x2 GEMM + fused attention-dot epilogue (R14 proven) ----------------
__global__ __launch_bounds__(128, 4) void gemm_kernel(
    const float* __restrict__ A, const float* __restrict__ B, __nv_bfloat16* __restrict__ C,
    int M, int N, int K,
    const float* __restrict__ avec, const float* __restrict__ dvec,
    float* __restrict__ as_out, float* __restrict__ ad_out, int multihead)
{
    __shared__ float As[16][68];
    __shared__ float Bs[16][132];

    int tid = threadIdx.x;
    int lane = tid & 31;
    int rowBase = blockIdx.x * 64;
    int colBase = blockIdx.y * 128;
    int tx = tid & 15;
    int ty = tid >> 4;

    ull acc[4][8];
#pragma unroll
    for (int p = 0; p < 4; p++)
#pragma unroll
        for (int j = 0; j < 8; j++) acc[p][j] = 0ull;

    for (int k0 = 0; k0 < K; k0 += 16) {
#pragma unroll
        for (int i = 0; i < 2; i++) {
            int fid = tid + 128 * i;
            int r = fid >> 2, kq = (fid & 3) * 4;
            int row = rowBase + r;
            float4 v = make_float4(0.f, 0.f, 0.f, 0.f);
            if (row < M) v = *(const float4*)(A + (long long)row * K + k0 + kq);
            As[kq + 0][r] = v.x; As[kq + 1][r] = v.y;
            As[kq + 2][r] = v.z; As[kq + 3][r] = v.w;
        }
#pragma unroll
        for (int i = 0; i < 4; i++) {
            int fid = tid + 128 * i;
            int rw = fid >> 5, cq = fid & 31;
            *(float4*)&Bs[rw][cq * 4] =
                *(const float4*)(B + (long long)(k0 + rw) * N + colBase + cq * 4);
        }
        __syncthreads();
#pragma unroll
        for (int kk = 0; kk < 16; kk++) {
            ulonglong2 a01 = *(const ulonglong2*)&As[kk][ty * 8];
            ulonglong2 a23 = *(const ulonglong2*)&As[kk][ty * 8 + 4];
            float4 b0 = *(const float4*)&Bs[kk][tx * 4];
            float4 b1 = *(const float4*)&Bs[kk][64 + tx * 4];
            ull rb[8];
            rb[0] = pack2(b0.x, b0.x); rb[1] = pack2(b0.y, b0.y);
            rb[2] = pack2(b0.z, b0.z); rb[3] = pack2(b0.w, b0.w);
            rb[4] = pack2(b1.x, b1.x); rb[5] = pack2(b1.y, b1.y);
            rb[6] = pack2(b1.z, b1.z); rb[7] = pack2(b1.w, b1.w);
            ull ra[4] = {a01.x, a01.y, a23.x, a23.y};
#pragma unroll
            for (int p = 0; p < 4; p++)
#pragma unroll
                for (int j = 0; j < 8; j++) ffma2(acc[p][j], ra[p], rb[j]);
        }
        __syncthreads();
    }

    float4 av0 = *(const float4*)(avec + colBase + tx * 4);
    float4 av1 = *(const float4*)(avec + colBase + 64 + tx * 4);
    float4 dv0 = *(const float4*)(dvec + colBase + tx * 4);
    float4 dv1 = *(const float4*)(dvec + colBase + 64 + tx * 4);
    float ds0[8], ds1[8], dd0[8], dd1[8];

#pragma unroll
    for (int p = 0; p < 4; p++) {
        float lo[8], hi[8];
#pragma unroll
        for (int j = 0; j < 8; j++) unpack2(lo[j], hi[j], acc[p][j]);
        int m0 = rowBase + ty * 8 + 2 * p;
        long long cb = (long long)m0 * N + colBase + tx * 4;
        if (m0 < M) {
            uint2 u0 = make_uint2(bfpack(lo[0], lo[1]), bfpack(lo[2], lo[3]));
            uint2 u1 = make_uint2(bfpack(lo[4], lo[5]), bfpack(lo[6], lo[7]));
            *(uint2*)(C + cb)      = u0;
            *(uint2*)(C + cb + 64) = u1;
        }
        if (m0 + 1 < M) {
            uint2 u0 = make_uint2(bfpack(hi[0], hi[1]), bfpack(hi[2], hi[3]));
            uint2 u1 = make_uint2(bfpack(hi[4], hi[5]), bfpack(hi[6], hi[7]));
            *(uint2*)(C + cb + N)      = u0;
            *(uint2*)(C + cb + N + 64) = u1;
        }
        ds0[2*p]   = lo[0]*av0.x + lo[1]*av0.y + lo[2]*av0.z + lo[3]*av0.w;
        ds1[2*p]   = lo[4]*av1.x + lo[5]*av1.y + lo[6]*av1.z + lo[7]*av1.w;
        dd0[2*p]   = lo[0]*dv0.x + lo[1]*dv0.y + lo[2]*dv0.z + lo[3]*dv0.w;
        dd1[2*p]   = lo[4]*dv1.x + lo[5]*dv1.y + lo[6]*dv1.z + lo[7]*dv1.w;
        ds0[2*p+1] = hi[0]*av0.x + hi[1]*av0.y + hi[2]*av0.z + hi[3]*av0.w;
        ds1[2*p+1] = hi[4]*av1.x + hi[5]*av1.y + hi[6]*av1.z + hi[7]*av1.w;
        dd0[2*p+1] = hi[0]*dv0.x + hi[1]*dv0.y + hi[2]*dv0.z + hi[3]*dv0.w;
        dd1[2*p+1] = hi[4]*dv1.x + hi[5]*dv1.y + hi[6]*dv1.z + hi[7]*dv1.w;
    }
    if (!multihead) {
#pragma unroll
        for (int rr = 0; rr < 8; rr++) { ds0[rr] += ds1[rr]; dd0[rr] += dd1[rr]; }
    }
#pragma unroll
    for (int rr = 0; rr < 8; rr++) {
#pragma unroll
        for (int off = 1; off <= 8; off <<= 1) {
            ds0[rr] += __shfl_xor_sync(0xffffffffu, ds0[rr], off);
            dd0[rr] += __shfl_xor_sync(0xffffffffu, dd0[rr], off);
        }
        if (multihead) {
#pragma unroll
            for (int off = 1; off <= 8; off <<= 1) {
                ds1[rr] += __shfl_xor_sync(0xffffffffu, ds1[rr], off);
                dd1[rr] += __shfl_xor_sync(0xffffffffu, dd1[rr], off);
            }
        }
    }
    int rowb = rowBase + ty * 8;
    if ((lane & 15) == 0) {
        if (multihead) {
            int h0 = colBase >> 6;
#pragma unroll
            for (int rr = 0; rr < 8; rr++) {
                int row = rowb + rr;
                if (row < M) {
                    as_out[row * 4 + h0]     = ds0[rr];
                    as_out[row * 4 + h0 + 1] = ds1[rr];
                    ad_out[row * 4 + h0]     = dd0[rr];
                    ad_out[row * 4 + h0 + 1] = dd1[rr];
                }
            }
        } else {
#pragma unroll
            for (int rr = 0; rr < 8; rr++) {
                int row = rowb + rr;
                if (row < M) {
                    as_out[row] = ds0[rr];
                    ad_out[row] = dd0[rr];
                }
            }
        }
    }
}

// ---------------- CSR aggregation (warp per dst node, R14 proven form) ----------------
__global__ __launch_bounds__(256) void agg1_kernel(const float* __restrict__ b1) {
    int d = (blockIdx.x * blockDim.x + threadIdx.x) >> 5;
    int lane = threadIdx.x & 31;
    if (d >= NN) return;
    int h = lane >> 3;
    float ad = g_ad1[d * 4 + h];
    int beg = g_rowptr[d], end = g_rowptr[d + 1];
    float z = 0.f;
    float a[8] = {0.f, 0.f, 0.f, 0.f, 0.f, 0.f, 0.f, 0.f};
    for (int i = beg; i < end; i++) {
        int s = g_csrc[i];
        float w = __expf(lrelu(g_as1[s * 4 + h] + ad));
        z += w;
        uint4 v = *(const uint4*)(g_h1 + (size_t)s * D1 + lane * 8);
        a[0] += w * bflo(v.x); a[1] += w * bfhi(v.x);
        a[2] += w * bflo(v.y); a[3] += w * bfhi(v.y);
        a[4] += w * bflo(v.z); a[5] += w * bfhi(v.z);
        a[6] += w * bflo(v.w); a[7] += w * bfhi(v.w);
    }
    float inv = 1.f / z;
    const float4* bb = (const float4*)(b1 + lane * 8);
    float4 c0 = bb[0], c1 = bb[1];
    float4 o0, o1;
    o0.x = elu1(a[0] * inv + c0.x); o0.y = elu1(a[1] * inv + c0.y);
    o0.z = elu1(a[2] * inv + c0.z); o0.w = elu1(a[3] * inv + c0.w);
    o1.x = elu1(a[4] * inv + c1.x); o1.y = elu1(a[5] * inv + c1.y);
    o1.z = elu1(a[6] * inv + c1.z); o1.w = elu1(a[7] * inv + c1.w);
    float4* op = (float4*)(g_act1 + (size_t)d * D1 + lane * 8);
    op[0] = o0; op[1] = o1;
}

__global__ __launch_bounds__(256) void agg2_kernel(const float* __restrict__ b2) {
    int d = (blockIdx.x * blockDim.x + threadIdx.x) >> 5;
    int lane = threadIdx.x & 31;
    if (d >= NN) return;
    float ad = g_ad2[d];
    int beg = g_rowptr[d], end = g_rowptr[d + 1];
    float z = 0.f;
    float a[4] = {0.f, 0.f, 0.f, 0.f};
    for (int i = beg; i < end; i++) {
        int s = g_csrc[i];
        float w = __expf(lrelu(g_as2[s] + ad));
        z += w;
        uint2 v = *(const uint2*)(g_h2 + (size_t)s * EMB + lane * 4);
        a[0] += w * bflo(v.x); a[1] += w * bfhi(v.x);
        a[2] += w * bflo(v.y); a[3] += w * bfhi(v.y);
    }
    float inv = 1.f / z;
    float4 c = ((const float4*)b2)[lane];
    float o0 = elu1(a[0] * inv + c.x), o1 = elu1(a[1] * inv + c.y);
    float o2 = elu1(a[2] * inv + c.z), o3 = elu1(a[3] * inv + c.w);
    int b = g_batch[d];
    red4(&g_pool[b * EMB + lane * 4], o0, o1, o2, o3);
}

// final divide + re-zero accumulator state for next graph replay
__global__ __launch_bounds__(256) void tail_kernel(float* __restrict__ out) {
    int i = blockIdx.x * blockDim.x + threadIdx.x;
    if (i < NG * EMB) {
        out[i] = g_pool[i] / fmaxf(g_cnt[i >> 7], 1.f);
        g_pool[i] = 0.f;
    }
    if (i < NN)  g_wp[i]  = 0;
    if (i < NG)  g_cnt[i] = 0.f;
}

// ---------------- launcher ----------------
extern "C" void kernel_launch(void* const* d_in, const int* in_sizes, int n_in,
                              void* d_out, int out_size)
{
    const float* x      = (const float*)d_in[0];
    const void*  ei     = d_in[1];
    const void*  batch  = d_in[3];
    const float* W1     = (const float*)d_in[4];
    const float* a_src1 = (const float*)d_in[5];
    const float* a_dst1 = (const float*)d_in[6];
    const float* b1     = (const float*)d_in[7];
    const float* W2     = (const float*)d_in[8];
    const float* a_src2 = (const float*)d_in[9];
    const float* a_dst2 = (const float*)d_in[10];
    const float* b2     = (const float*)d_in[11];
    float*       out    = (float*)d_out;

    __nv_bfloat16 *p_h1, *p_h2;
    float *p_act1, *p_as1, *p_ad1, *p_as2, *p_ad2;
    cudaGetSymbolAddress((void**)&p_h1,   g_h1);
    cudaGetSymbolAddress((void**)&p_act1, g_act1);
    cudaGetSymbolAddress((void**)&p_h2,   g_h2);
    cudaGetSymbolAddress((void**)&p_as1,  g_as1);
    cudaGetSymbolAddress((void**)&p_ad1,  g_ad1);
    cudaGetSymbolAddress((void**)&p_as2,  g_as2);
    cudaGetSymbolAddress((void**)&p_ad2,  g_ad2);

    static cudaStream_t s_side = nullptr;
    static cudaEvent_t  ev_fork = nullptr, ev_join = nullptr;
    if (!s_side) {
        cudaStreamCreateWithFlags(&s_side, cudaStreamNonBlocking);
        cudaEventCreateWithFlags(&ev_fork, cudaEventDisableTiming);
        cudaEventCreateWithFlags(&ev_join, cudaEventDisableTiming);
    }

    // fork: 2-kernel CSR build (prep+scan fused) concurrent with GEMM1.
    // agg1 is the 4th-submitted launch -> profiled this round.
    cudaEventRecord(ev_fork, 0);
    cudaStreamWaitEvent(s_side, ev_fork, 0);
    prepscan_kernel<<<(NET + 255) / 256, 256, 0, s_side>>>(ei, batch);   // 1
    fill_kernel<<<(NET + 255) / 256, 256, 0, s_side>>>();                // 2
    cudaEventRecord(ev_join, s_side);

    gemm_kernel<<<dim3((NN + 63) / 64, D1 / 128), 128>>>(                // 3
        x, W1, p_h1, NN, D1, IND, a_src1, a_dst1, p_as1, p_ad1, 1);

    cudaStreamWaitEvent(0, ev_join, 0);
    agg1_kernel<<<(NN + 7) / 8, 256>>>(b1);                              // 4 <- profiled

    gemm_kernel<<<dim3((NN + 63) / 64, EMB / 128), 128>>>(               // 5
        p_act1, W2, p_h2, NN, EMB, D1, a_src2, a_dst2, p_as2, p_ad2, 0);
    agg2_kernel<<<(NN + 7) / 8, 256>>>(b2);                              // 6
    tail_kernel<<<(NN + 255) / 256, 256>>>(out);                         // 7
}